// round 1
// baseline (speedup 1.0000x reference)
#include <cuda_runtime.h>
#include <cstdint>

// Morton encode permutation: out[s, morton(i,j)] = in[s, i, j]
// x: (8, 64, 256, 256) fp32 -> 512 slices of 256x256.
// Each thread produces 8 consecutive Morton outputs (low 3 bits of m = j0,i0,j1),
// which correspond to a 2x4 input block: two float4 loads, two float4 stores.

static constexpr int N = 256;
static constexpr int SLICE = N * N;          // 65536
static constexpr int ELEMS_PER_THREAD = 8;
static constexpr int THREADS_PER_SLICE = SLICE / ELEMS_PER_THREAD;  // 8192

__device__ __forceinline__ unsigned deinterleave16(unsigned v) {
    // compact even bits of a 16-bit value into low 8 bits
    v &= 0x5555u;
    v = (v | (v >> 1)) & 0x3333u;
    v = (v | (v >> 2)) & 0x0F0Fu;
    v = (v | (v >> 4)) & 0x00FFu;
    return v;
}

__global__ void __launch_bounds__(256) morton_kernel(const float* __restrict__ in,
                                                     float* __restrict__ out,
                                                     int total_threads) {
    int t = blockIdx.x * blockDim.x + threadIdx.x;
    if (t >= total_threads) return;

    unsigned s = (unsigned)t >> 13;                 // slice id (t / 8192)
    unsigned m = ((unsigned)t & (THREADS_PER_SLICE - 1)) << 3;  // base morton index, low 3 bits zero

    unsigned j = deinterleave16(m);        // even bits -> column
    unsigned i = deinterleave16(m >> 1);   // odd bits  -> row
    // m % 8 == 0 => j % 4 == 0, i % 2 == 0

    const float* slice_in = in + (size_t)s * SLICE;
    const float4 a = *reinterpret_cast<const float4*>(slice_in + (size_t)i * N + j);
    const float4 b = *reinterpret_cast<const float4*>(slice_in + (size_t)(i + 1) * N + j);

    float4* ob = reinterpret_cast<float4*>(out + (size_t)t * ELEMS_PER_THREAD);
    // m+0:(i,j) m+1:(i,j+1) m+2:(i+1,j) m+3:(i+1,j+1)
    // m+4:(i,j+2) m+5:(i,j+3) m+6:(i+1,j+2) m+7:(i+1,j+3)
    ob[0] = make_float4(a.x, a.y, b.x, b.y);
    ob[1] = make_float4(a.z, a.w, b.z, b.w);
}

extern "C" void kernel_launch(void* const* d_in, const int* in_sizes, int n_in,
                              void* d_out, int out_size) {
    const float* in = (const float*)d_in[0];
    float* out = (float*)d_out;

    int total_elems = in_sizes[0];                       // 33,554,432
    int total_threads = total_elems / ELEMS_PER_THREAD;  // 4,194,304

    int block = 256;
    int grid = (total_threads + block - 1) / block;      // 16384
    morton_kernel<<<grid, block>>>(in, out, total_threads);
}